// round 7
// baseline (speedup 1.0000x reference)
#include <cuda_runtime.h>
#include <cuda_fp16.h>
#include <cstdint>

// Problem constants (match reference)
#define N_USERS 200000
#define N_ITEMS 400000
#define N_NODES 600000
#define EMB_DIM 128
#define N_EDGES 3000000
#define VEC4_PER_ROW 32
#define TOTAL_F ((size_t)N_NODES * EMB_DIM)   // 76.8M elems
#define TOTAL_V4 (TOTAL_F / 4)

#define BIN_SPLIT 300000              // cols < split -> bin 0, else bin 1
#define M_KEYS (2 * N_NODES)          // 1.2M virtual rows (bin-major)
#define SCAN_T 1024
#define SCAN_ELEMS 2048               // 2 elements per thread
#define N_SCAN_BLOCKS ((M_KEYS + SCAN_ELEMS - 1) / SCAN_ELEMS)  // 586

// Static scratch (allowed: __device__ globals; zero-init on load)
__device__ __half g_bufX[TOTAL_F];       // fp16 inputs; reused as L3 partial
__device__ __half g_bufA[TOTAL_F];
__device__ __half g_bufB[TOTAL_F];
__device__ int    g_count[M_KEYS];       // zeroed every replay by scan1
__device__ int    g_offsetL[M_KEYS];     // block-local exclusive scan
__device__ int    g_pos[M_KEYS];
__device__ int    g_bsum[SCAN_T];        // >= N_SCAN_BLOCKS
__device__ int2   g_pair[N_EDGES];       // (col, val-as-int), bin-major CSR

// ---------------------------------------------------------------------------
// Launch 1: histogram over (bin,row) keys + fp32->fp16 input conversion
// ---------------------------------------------------------------------------
__global__ void hist_convert_kernel(const int* __restrict__ rows,
                                    const int* __restrict__ cols,
                                    int* __restrict__ count,
                                    const float4* __restrict__ user,
                                    const float4* __restrict__ item,
                                    uint2* __restrict__ X2) {
    size_t tid = (size_t)blockIdx.x * blockDim.x + threadIdx.x;
    if (tid < N_EDGES) {
        int key = rows[tid] + ((cols[tid] >= BIN_SPLIT) ? N_NODES : 0);
        atomicAdd(&count[key], 1);
    }
    const size_t user_v4 = (size_t)N_USERS * VEC4_PER_ROW;
    size_t stride = (size_t)gridDim.x * blockDim.x;
    for (size_t i = tid; i < TOTAL_V4; i += stride) {
        float4 v = (i < user_v4) ? __ldg(user + i) : __ldg(item + i - user_v4);
        __half2 h0 = __floats2half2_rn(v.x, v.y);
        __half2 h1 = __floats2half2_rn(v.z, v.w);
        uint2 raw;
        raw.x = *reinterpret_cast<unsigned*>(&h0);
        raw.y = *reinterpret_cast<unsigned*>(&h1);
        X2[i] = raw;
    }
}

// ---------------------------------------------------------------------------
// Launch 2: block-local exclusive scan (2048 elems/block); zero count; seed pos
// ---------------------------------------------------------------------------
__global__ void scan1_kernel(int* __restrict__ count,
                             int* __restrict__ offsetL,
                             int* __restrict__ pos,
                             int* __restrict__ bsum) {
    __shared__ int sh[SCAN_T];
    int base = blockIdx.x * SCAN_ELEMS;
    int i0 = base + 2 * threadIdx.x;
    int i1 = i0 + 1;
    int v0 = (i0 < M_KEYS) ? count[i0] : 0;
    int v1 = (i1 < M_KEYS) ? count[i1] : 0;
    if (i0 < M_KEYS) count[i0] = 0;   // restore replay invariant
    if (i1 < M_KEYS) count[i1] = 0;
    int s = v0 + v1;
    sh[threadIdx.x] = s;
    __syncthreads();
    #pragma unroll
    for (int d = 1; d < SCAN_T; d <<= 1) {
        int t = (threadIdx.x >= d) ? sh[threadIdx.x - d] : 0;
        __syncthreads();
        sh[threadIdx.x] += t;
        __syncthreads();
    }
    int incl = sh[threadIdx.x];
    int e0 = incl - s;        // exclusive for i0
    int e1 = incl - v1;       // exclusive for i1
    if (i0 < M_KEYS) { offsetL[i0] = e0; pos[i0] = e0; }
    if (i1 < M_KEYS) { offsetL[i1] = e1; pos[i1] = e1; }
    if (threadIdx.x == SCAN_T - 1) bsum[blockIdx.x] = incl;
}

// ---------------------------------------------------------------------------
// Launch 3: exclusive scan of block sums (single block, 586 entries)
// ---------------------------------------------------------------------------
__global__ void scan2_kernel(int* __restrict__ bsum, int nb) {
    __shared__ int sh[SCAN_T];
    int v = (threadIdx.x < nb) ? bsum[threadIdx.x] : 0;
    sh[threadIdx.x] = v;
    __syncthreads();
    #pragma unroll
    for (int d = 1; d < SCAN_T; d <<= 1) {
        int t = (threadIdx.x >= d) ? sh[threadIdx.x - d] : 0;
        __syncthreads();
        sh[threadIdx.x] += t;
        __syncthreads();
    }
    if (threadIdx.x < nb) bsum[threadIdx.x] = sh[threadIdx.x] - v;
}

// ---------------------------------------------------------------------------
// Launch 4: permute edges into bin-major CSR order
// ---------------------------------------------------------------------------
__global__ void permute_kernel(const int* __restrict__ rows,
                               const int* __restrict__ cols,
                               const float* __restrict__ vals,
                               int* __restrict__ pos,
                               const int* __restrict__ bsum,
                               int2* __restrict__ pair) {
    int e = blockIdx.x * blockDim.x + threadIdx.x;
    if (e >= N_EDGES) return;
    int c = cols[e];
    int key = rows[e] + ((c >= BIN_SPLIT) ? N_NODES : 0);
    int p = atomicAdd(&pos[key], 1) + __ldg(&bsum[key >> 11]);
    int2 pr;
    pr.x = c;
    pr.y = __float_as_int(vals[e]);
    pair[p] = pr;
}

// ---------------------------------------------------------------------------
// fp16 row helpers (8B per lane). _s variants: streaming (evict-first).
// ---------------------------------------------------------------------------
__device__ __forceinline__ float4 h4_unpack(uint2 raw) {
    __half2 h0 = *reinterpret_cast<__half2*>(&raw.x);
    __half2 h1 = *reinterpret_cast<__half2*>(&raw.y);
    float2 f0 = __half22float2(h0);
    float2 f1 = __half22float2(h1);
    return make_float4(f0.x, f0.y, f1.x, f1.y);
}
__device__ __forceinline__ float4 load_h4(const __half* row, int lane) {
    return h4_unpack(__ldg(reinterpret_cast<const uint2*>(row) + lane));
}
__device__ __forceinline__ float4 load_h4_s(const __half* row, int lane) {
    return h4_unpack(__ldcs(reinterpret_cast<const uint2*>(row) + lane));
}
__device__ __forceinline__ uint2 h4_pack(float4 v) {
    __half2 h0 = __floats2half2_rn(v.x, v.y);
    __half2 h1 = __floats2half2_rn(v.z, v.w);
    uint2 raw;
    raw.x = *reinterpret_cast<unsigned*>(&h0);
    raw.y = *reinterpret_cast<unsigned*>(&h1);
    return raw;
}
__device__ __forceinline__ void store_h4_s(__half* row, int lane, float4 v) {
    __stcs(reinterpret_cast<uint2*>(row) + lane, h4_pack(v));
}

// ---------------------------------------------------------------------------
// SpMM pass: warp-per-row, gather restricted to one col bin (L2-resident).
// MODE 0: first pass  -> dst = acc
// MODE 1: second pass -> dst = dst + acc
// MODE 2: second pass, fused epilogue -> out = 0.25*(x0 + A + B + (part+acc))
// Streams (pair, partial, dst, epilogue rows) use .cs to protect hot bin in L2.
// ---------------------------------------------------------------------------
template <int MODE>
__global__ void __launch_bounds__(512)
spmm_kernel(const int* __restrict__ offsetL,
            const int* __restrict__ bsum,
            const int2* __restrict__ pair,
            const __half* __restrict__ srcH,   // gather source
            __half* __restrict__ dstH,         // MODE 0/1 dst
            const __half* __restrict__ partH,  // MODE 2: partial (X)
            const __half* __restrict__ accA,   // MODE 2
            const __half* __restrict__ accB,   // MODE 2
            const float4* __restrict__ u,      // MODE 2: fp32 inputs
            const float4* __restrict__ it,
            float4* __restrict__ out,          // MODE 2
            int keyBase) {                     // 0 (bin0) or N_NODES (bin1)
    int lane = threadIdx.x & 31;
    int r = (blockIdx.x * blockDim.x + threadIdx.x) >> 5;
    if (r >= N_NODES) return;
    int key = keyBase + r;

    int j = __ldg(offsetL + key) + __ldg(bsum + (key >> 11));
    int end = (key == M_KEYS - 1)
                  ? N_EDGES
                  : __ldg(offsetL + key + 1) + __ldg(bsum + ((key + 1) >> 11));

    float4 acc0 = make_float4(0.f, 0.f, 0.f, 0.f);
    float4 acc1 = make_float4(0.f, 0.f, 0.f, 0.f);

    #pragma unroll 1
    for (; j + 2 <= end; j += 2) {
        int2 e0 = __ldcs(pair + j);
        int2 e1 = __ldcs(pair + j + 1);
        float4 m0 = load_h4(srcH + (size_t)e0.x * EMB_DIM, lane);
        float4 m1 = load_h4(srcH + (size_t)e1.x * EMB_DIM, lane);
        float v0 = __int_as_float(e0.y);
        float v1 = __int_as_float(e1.y);
        acc0.x += v0 * m0.x; acc0.y += v0 * m0.y;
        acc0.z += v0 * m0.z; acc0.w += v0 * m0.w;
        acc1.x += v1 * m1.x; acc1.y += v1 * m1.y;
        acc1.z += v1 * m1.z; acc1.w += v1 * m1.w;
    }
    if (j < end) {
        int2 e0 = __ldcs(pair + j);
        float4 m0 = load_h4(srcH + (size_t)e0.x * EMB_DIM, lane);
        float v0 = __int_as_float(e0.y);
        acc0.x += v0 * m0.x; acc0.y += v0 * m0.y;
        acc0.z += v0 * m0.z; acc0.w += v0 * m0.w;
    }

    float4 acc;
    acc.x = acc0.x + acc1.x; acc.y = acc0.y + acc1.y;
    acc.z = acc0.z + acc1.z; acc.w = acc0.w + acc1.w;

    size_t rowOff = (size_t)r * EMB_DIM;
    if (MODE == 0) {
        store_h4_s(dstH + rowOff, lane, acc);
    } else if (MODE == 1) {
        float4 p = load_h4_s(dstH + rowOff, lane);
        acc.x += p.x; acc.y += p.y; acc.z += p.z; acc.w += p.w;
        store_h4_s(dstH + rowOff, lane, acc);
    } else {
        float4 p = load_h4_s(partH + rowOff, lane);   // y3 partial
        float4 a = load_h4_s(accA + rowOff, lane);
        float4 b = load_h4_s(accB + rowOff, lane);
        size_t idx = (size_t)r * VEC4_PER_ROW + lane;
        float4 x0 = (r < N_USERS)
                        ? __ldcs(u + (size_t)r * VEC4_PER_ROW + lane)
                        : __ldcs(it + (size_t)(r - N_USERS) * VEC4_PER_ROW + lane);
        float4 o;
        o.x = 0.25f * (x0.x + a.x + b.x + (p.x + acc.x));
        o.y = 0.25f * (x0.y + a.y + b.y + (p.y + acc.y));
        o.z = 0.25f * (x0.z + a.z + b.z + (p.z + acc.z));
        o.w = 0.25f * (x0.w + a.w + b.w + (p.w + acc.w));
        __stcs(out + idx, o);
    }
}

extern "C" void kernel_launch(void* const* d_in, const int* in_sizes, int n_in,
                              void* d_out, int out_size) {
    const float4* emb_user = (const float4*)d_in[0];
    const float4* emb_item = (const float4*)d_in[1];
    const int* edge_row = (const int*)d_in[2];
    const int* edge_col = (const int*)d_in[3];
    const float* edge_val = (const float*)d_in[4];
    float4* out = (float4*)d_out;

    __half *X, *A, *B;
    int *count_, *offsetL_, *pos_, *bsum_;
    int2 *pair_;
    cudaGetSymbolAddress((void**)&X, g_bufX);
    cudaGetSymbolAddress((void**)&A, g_bufA);
    cudaGetSymbolAddress((void**)&B, g_bufB);
    cudaGetSymbolAddress((void**)&count_, g_count);
    cudaGetSymbolAddress((void**)&offsetL_, g_offsetL);
    cudaGetSymbolAddress((void**)&pos_, g_pos);
    cudaGetSymbolAddress((void**)&bsum_, g_bsum);
    cudaGetSymbolAddress((void**)&pair_, g_pair);

    const int T = 256;
    const int gridEdge = (N_EDGES + T - 1) / T;
    const int TS = 512;
    const int gridRow = (int)(((size_t)N_NODES * 32 + TS - 1) / TS);

    // ---- build: histogram(+convert), scans, permute (bin-major CSR) ----
    hist_convert_kernel<<<gridEdge, T>>>(edge_row, edge_col, count_,
                                         emb_user, emb_item, (uint2*)X);
    scan1_kernel<<<N_SCAN_BLOCKS, SCAN_T>>>(count_, offsetL_, pos_, bsum_);
    scan2_kernel<<<1, SCAN_T>>>(bsum_, N_SCAN_BLOCKS);
    permute_kernel<<<gridEdge, T>>>(edge_row, edge_col, edge_val,
                                    pos_, bsum_, pair_);

    // ---- Layer 1: X -> A (bin0 write, bin1 accumulate) ----
    spmm_kernel<0><<<gridRow, TS>>>(offsetL_, bsum_, pair_, X, A,
                                    nullptr, nullptr, nullptr,
                                    nullptr, nullptr, nullptr, 0);
    spmm_kernel<1><<<gridRow, TS>>>(offsetL_, bsum_, pair_, X, A,
                                    nullptr, nullptr, nullptr,
                                    nullptr, nullptr, nullptr, N_NODES);
    // ---- Layer 2: A -> B ----
    spmm_kernel<0><<<gridRow, TS>>>(offsetL_, bsum_, pair_, A, B,
                                    nullptr, nullptr, nullptr,
                                    nullptr, nullptr, nullptr, 0);
    spmm_kernel<1><<<gridRow, TS>>>(offsetL_, bsum_, pair_, A, B,
                                    nullptr, nullptr, nullptr,
                                    nullptr, nullptr, nullptr, N_NODES);
    // ---- Layer 3: B -> (X as partial), then fused epilogue -> out ----
    spmm_kernel<0><<<gridRow, TS>>>(offsetL_, bsum_, pair_, B, X,
                                    nullptr, nullptr, nullptr,
                                    nullptr, nullptr, nullptr, 0);
    spmm_kernel<2><<<gridRow, TS>>>(offsetL_, bsum_, pair_, B, nullptr,
                                    X, A, B, emb_user, emb_item, out, N_NODES);
}

// round 9
// speedup vs baseline: 1.6415x; 1.6415x over previous
#include <cuda_runtime.h>
#include <cuda_fp16.h>
#include <cstdint>

// Problem constants (match reference)
#define N_USERS 200000
#define N_ITEMS 400000
#define N_NODES 600000
#define EMB_DIM 128
#define N_EDGES 3000000
#define VEC4_PER_ROW 32
#define TOTAL_F ((size_t)N_NODES * EMB_DIM)   // 76.8M elems
#define TOTAL_V4 (TOTAL_F / 4)

#define SCAN_BLOCK 1024
#define N_SCAN_BLOCKS ((N_NODES + SCAN_BLOCK - 1) / SCAN_BLOCK)  // 586

// Static scratch (allowed: __device__ globals; zero-init on load)
// 256B-aligned: rows are 256B, gathered with 32B (256-bit) loads.
__device__ __align__(256) __half g_bufX[TOTAL_F];   // fp16 inputs, 153.6 MB
__device__ __align__(256) __half g_bufA[TOTAL_F];
__device__ __align__(256) __half g_bufB[TOTAL_F];
__device__ int  g_count[N_NODES];    // re-zeroed every replay by scan1
__device__ int  g_offsetL[N_NODES];  // block-local exclusive scan
__device__ int  g_pos[N_NODES];
__device__ int  g_bsum[SCAN_BLOCK];  // >= N_SCAN_BLOCKS
__device__ int2 g_pair[N_EDGES];     // (col, val-as-int) packed, CSR order

// ---------------------------------------------------------------------------
// Launch 1: histogram + (grid-stride) fp32->fp16 input conversion fused
// ---------------------------------------------------------------------------
__global__ void hist_convert_kernel(const int* __restrict__ rows,
                                    int* __restrict__ count,
                                    const float4* __restrict__ user,
                                    const float4* __restrict__ item,
                                    uint2* __restrict__ X2) {
    size_t tid = (size_t)blockIdx.x * blockDim.x + threadIdx.x;
    if (tid < N_EDGES) atomicAdd(&count[rows[tid]], 1);

    const size_t user_v4 = (size_t)N_USERS * VEC4_PER_ROW;
    size_t stride = (size_t)gridDim.x * blockDim.x;
    for (size_t i = tid; i < TOTAL_V4; i += stride) {
        float4 v = (i < user_v4) ? __ldcs(user + i) : __ldcs(item + i - user_v4);
        __half2 h0 = __floats2half2_rn(v.x, v.y);
        __half2 h1 = __floats2half2_rn(v.z, v.w);
        uint2 raw;
        raw.x = *reinterpret_cast<unsigned*>(&h0);
        raw.y = *reinterpret_cast<unsigned*>(&h1);
        __stcs(X2 + i, raw);   // streaming
    }
}

// ---------------------------------------------------------------------------
// Launch 2: block-local exclusive scan; zeroes count; seeds pos
// ---------------------------------------------------------------------------
__global__ void scan1_kernel(int* __restrict__ count,
                             int* __restrict__ offsetL,
                             int* __restrict__ pos,
                             int* __restrict__ bsum) {
    __shared__ int sh[SCAN_BLOCK];
    int i = blockIdx.x * SCAN_BLOCK + threadIdx.x;
    int v = (i < N_NODES) ? count[i] : 0;
    if (i < N_NODES) count[i] = 0;   // restore replay invariant
    sh[threadIdx.x] = v;
    __syncthreads();
    #pragma unroll
    for (int d = 1; d < SCAN_BLOCK; d <<= 1) {
        int t = (threadIdx.x >= d) ? sh[threadIdx.x - d] : 0;
        __syncthreads();
        sh[threadIdx.x] += t;
        __syncthreads();
    }
    if (i < N_NODES) {
        int excl = sh[threadIdx.x] - v;
        offsetL[i] = excl;
        pos[i] = excl;
    }
    if (threadIdx.x == SCAN_BLOCK - 1) bsum[blockIdx.x] = sh[SCAN_BLOCK - 1];
}

// ---------------------------------------------------------------------------
// Launch 3: exclusive scan of block sums (single block)
// ---------------------------------------------------------------------------
__global__ void scan2_kernel(int* __restrict__ bsum, int nb) {
    __shared__ int sh[SCAN_BLOCK];
    int v = (threadIdx.x < nb) ? bsum[threadIdx.x] : 0;
    sh[threadIdx.x] = v;
    __syncthreads();
    #pragma unroll
    for (int d = 1; d < SCAN_BLOCK; d <<= 1) {
        int t = (threadIdx.x >= d) ? sh[threadIdx.x - d] : 0;
        __syncthreads();
        sh[threadIdx.x] += t;
        __syncthreads();
    }
    if (threadIdx.x < nb) bsum[threadIdx.x] = sh[threadIdx.x] - v;  // exclusive
}

// ---------------------------------------------------------------------------
// Launch 4: permute edges into CSR order (global offset = local + bsum)
// ---------------------------------------------------------------------------
__global__ void permute_kernel(const int* __restrict__ rows,
                               const int* __restrict__ cols,
                               const float* __restrict__ vals,
                               int* __restrict__ pos,
                               const int* __restrict__ bsum,
                               int2* __restrict__ pair) {
    int e = blockIdx.x * blockDim.x + threadIdx.x;
    if (e >= N_EDGES) return;
    int r = rows[e];
    int p = atomicAdd(&pos[r], 1) + __ldg(&bsum[r >> 10]);
    int2 pr;
    pr.x = cols[e];
    pr.y = __float_as_int(vals[e]);
    __stcs(pair + p, pr);    // streaming scatter
}

// ---------------------------------------------------------------------------
// Gather: 32B (256-bit) load with L2 evict_last (pins source rows in L2),
// unpack 16 halfs, FMA into 16 fp32 accumulators.
// ---------------------------------------------------------------------------
__device__ __forceinline__ void gather_acc(const __half* __restrict__ srcH,
                                           int col, int sub, float v,
                                           float* acc) {
    const char* p = reinterpret_cast<const char*>(srcH)
                    + ((size_t)col << 8) + (sub << 5);
    uint32_t q0, q1, q2, q3, q4, q5, q6, q7;
    asm volatile(
        "ld.global.nc.L2::evict_last.v8.b32 {%0,%1,%2,%3,%4,%5,%6,%7}, [%8];"
        : "=r"(q0), "=r"(q1), "=r"(q2), "=r"(q3),
          "=r"(q4), "=r"(q5), "=r"(q6), "=r"(q7)
        : "l"(p));
    uint32_t q[8] = {q0, q1, q2, q3, q4, q5, q6, q7};
    #pragma unroll
    for (int i = 0; i < 8; ++i) {
        __half2 h = *reinterpret_cast<__half2*>(&q[i]);
        float2 f = __half22float2(h);
        acc[2 * i]     += v * f.x;
        acc[2 * i + 1] += v * f.y;
    }
}

__device__ __forceinline__ void unpack16(uint4 lo, uint4 hi, float* f) {
    uint32_t q[8] = {lo.x, lo.y, lo.z, lo.w, hi.x, hi.y, hi.z, hi.w};
    #pragma unroll
    for (int i = 0; i < 8; ++i) {
        __half2 h = *reinterpret_cast<__half2*>(&q[i]);
        float2 t = __half22float2(h);
        f[2 * i] = t.x;
        f[2 * i + 1] = t.y;
    }
}

// ---------------------------------------------------------------------------
// Launches 5-7: pull SpMM. One 8-lane group per row; lane owns 16 elements
// (32B fp16). Gather via LDG.256 + L2::evict_last. fp32 accumulation.
// FUSED (layer 3): out = 0.25*(x0_fp32 + A + B + y)
// ---------------------------------------------------------------------------
template <bool FUSED>
__global__ void __launch_bounds__(256)
spmm_kernel(const int* __restrict__ offsetL,
            const int* __restrict__ bsum,
            const int2* __restrict__ pair,
            const __half* __restrict__ xH,    // gather src (fp16, L2-pinned)
            __half* __restrict__ dstH,        // layer output (fp16)
            const float4* __restrict__ u,     // FUSED: user embs fp32
            const float4* __restrict__ it,    // FUSED: item embs fp32
            const __half* __restrict__ accA,  // FUSED: layer-1 out
            const __half* __restrict__ accB,  // FUSED: layer-2 out
            float4* __restrict__ out) {       // FUSED: final out fp32
    int sub = threadIdx.x & 7;                           // lane within group
    int r = (blockIdx.x * blockDim.x + threadIdx.x) >> 3; // group id = row
    if (r >= N_NODES) return;

    int j = __ldg(offsetL + r) + __ldg(bsum + (r >> 10));
    int end = (r == N_NODES - 1)
                  ? N_EDGES
                  : __ldg(offsetL + r + 1) + __ldg(bsum + ((r + 1) >> 10));

    float acc[16];
    #pragma unroll
    for (int k = 0; k < 16; ++k) acc[k] = 0.f;

    #pragma unroll 1
    for (; j + 2 <= end; j += 2) {
        int2 e0 = __ldcs(pair + j);        // 8 lanes same addr: broadcast
        int2 e1 = __ldcs(pair + j + 1);
        gather_acc(xH, e0.x, sub, __int_as_float(e0.y), acc);
        gather_acc(xH, e1.x, sub, __int_as_float(e1.y), acc);
    }
    if (j < end) {
        int2 e0 = __ldcs(pair + j);
        gather_acc(xH, e0.x, sub, __int_as_float(e0.y), acc);
    }

    if (FUSED) {
        // lane owns elements [16*sub, 16*sub+15] of row r
        const uint4* aRow = reinterpret_cast<const uint4*>(accA + (size_t)r * EMB_DIM);
        const uint4* bRow = reinterpret_cast<const uint4*>(accB + (size_t)r * EMB_DIM);
        float a[16], b[16];
        unpack16(__ldcs(aRow + 2 * sub), __ldcs(aRow + 2 * sub + 1), a);
        unpack16(__ldcs(bRow + 2 * sub), __ldcs(bRow + 2 * sub + 1), b);

        const float4* xr = (r < N_USERS)
                               ? (u + (size_t)r * VEC4_PER_ROW)
                               : (it + (size_t)(r - N_USERS) * VEC4_PER_ROW);
        float4* orow = out + (size_t)r * VEC4_PER_ROW + 4 * sub;
        #pragma unroll
        for (int q = 0; q < 4; ++q) {
            float4 x0 = __ldcs(xr + 4 * sub + q);
            float4 o;
            o.x = 0.25f * (x0.x + a[4 * q + 0] + b[4 * q + 0] + acc[4 * q + 0]);
            o.y = 0.25f * (x0.y + a[4 * q + 1] + b[4 * q + 1] + acc[4 * q + 1]);
            o.z = 0.25f * (x0.z + a[4 * q + 2] + b[4 * q + 2] + acc[4 * q + 2]);
            o.w = 0.25f * (x0.w + a[4 * q + 3] + b[4 * q + 3] + acc[4 * q + 3]);
            __stcs(orow + q, o);
        }
    } else {
        // pack 16 fp32 -> 16 fp16 -> two uint4 streaming stores (32B)
        uint32_t q[8];
        #pragma unroll
        for (int i = 0; i < 8; ++i) {
            __half2 h = __floats2half2_rn(acc[2 * i], acc[2 * i + 1]);
            q[i] = *reinterpret_cast<unsigned*>(&h);
        }
        uint4* drow = reinterpret_cast<uint4*>(dstH + (size_t)r * EMB_DIM) + 2 * sub;
        __stcs(drow, make_uint4(q[0], q[1], q[2], q[3]));
        __stcs(drow + 1, make_uint4(q[4], q[5], q[6], q[7]));
    }
}

extern "C" void kernel_launch(void* const* d_in, const int* in_sizes, int n_in,
                              void* d_out, int out_size) {
    const float4* emb_user = (const float4*)d_in[0];
    const float4* emb_item = (const float4*)d_in[1];
    const int* edge_row = (const int*)d_in[2];
    const int* edge_col = (const int*)d_in[3];
    const float* edge_val = (const float*)d_in[4];
    float4* out = (float4*)d_out;

    __half *X, *A, *B;
    int *count_, *offsetL_, *pos_, *bsum_;
    int2 *pair_;
    cudaGetSymbolAddress((void**)&X, g_bufX);
    cudaGetSymbolAddress((void**)&A, g_bufA);
    cudaGetSymbolAddress((void**)&B, g_bufB);
    cudaGetSymbolAddress((void**)&count_, g_count);
    cudaGetSymbolAddress((void**)&offsetL_, g_offsetL);
    cudaGetSymbolAddress((void**)&pos_, g_pos);
    cudaGetSymbolAddress((void**)&bsum_, g_bsum);
    cudaGetSymbolAddress((void**)&pair_, g_pair);

    const int T = 256;
    const int gridEdge = (N_EDGES + T - 1) / T;
    const int TS = 256;                                   // 32 rows per block
    const int gridRow = (int)(((size_t)N_NODES * 8 + TS - 1) / TS);

    // ---- build: histogram(+convert), scans, permute ----
    hist_convert_kernel<<<gridEdge, T>>>(edge_row, count_,
                                         emb_user, emb_item, (uint2*)X);
    scan1_kernel<<<N_SCAN_BLOCKS, SCAN_BLOCK>>>(count_, offsetL_, pos_, bsum_);
    scan2_kernel<<<1, SCAN_BLOCK>>>(bsum_, N_SCAN_BLOCKS);
    permute_kernel<<<gridEdge, T>>>(edge_row, edge_col, edge_val,
                                    pos_, bsum_, pair_);

    // ---- Layer 1: gather X -> A ----
    spmm_kernel<false><<<gridRow, TS>>>(offsetL_, bsum_, pair_, X, A,
                                        nullptr, nullptr, nullptr, nullptr,
                                        nullptr);
    // ---- Layer 2: gather A -> B ----
    spmm_kernel<false><<<gridRow, TS>>>(offsetL_, bsum_, pair_, A, B,
                                        nullptr, nullptr, nullptr, nullptr,
                                        nullptr);
    // ---- Layer 3 fused: gather B, out = 0.25*(x0 + A + B + y) ----
    spmm_kernel<true><<<gridRow, TS>>>(offsetL_, bsum_, pair_, B, nullptr,
                                       emb_user, emb_item, A, B, out);
}